// round 8
// baseline (speedup 1.0000x reference)
#include <cuda_runtime.h>
#include <cuda_fp16.h>
#include <cstdint>

// ---------------------------------------------------------------------------
// QFeedForward: out = relu( (cos(theta)*cos(x[...,:4])) @ W1^T ) @ W2^T
// fp16 mma.sync.m16n8k16 (compute_100 target: no tcgen05 available).
// GEMM M=32768, N=512, K=2048. CTA tile 128x128, 4 warps of 64x64 each,
// 128 threads/CTA, 2 CTAs/SM. K-chunk 64, double-buffered SW128 SMEM,
// ldmatrix.x4 fragment loads with REGISTER DOUBLE-BUFFERING (software
// pipeline: frags of ks+1 load while MMAs of ks issue), fp32 accumulate.
// ---------------------------------------------------------------------------

#define NTOK 32768
#define EDIM 512
#define FFN  2048

#define BM 128
#define BN 128
#define BK 64
#define KTILES (FFN / BK)            // 32
#define NTHREADS 128

#define SM_ABUF 16384                // 128 rows x 128B (64 halfs), SW128
#define SM_BBUF 16384                // 128 rows x 128B
#define SM_B0   (2 * SM_ABUF)
#define SMEM_TOTAL (2 * SM_ABUF + 2 * SM_BBUF)   // 65536 B -> 2 CTAs/SM

__device__ __half g_w2h[EDIM * FFN];   // W2 pre-rounded to fp16 (2 MB)

__device__ __forceinline__ uint32_t smem_u32(const void* p) {
    uint32_t a;
    asm("{ .reg .u64 t; cvta.to.shared.u64 t, %1; cvt.u32.u64 %0, t; }" : "=r"(a) : "l"(p));
    return a;
}

// ---------------------------------------------------------------------------
// W2 -> fp16 (one float4 -> 8 bytes per thread)
// ---------------------------------------------------------------------------
__global__ void w2cvt_kernel(const float* __restrict__ W2) {
    int i = blockIdx.x * blockDim.x + threadIdx.x;   // float4 index
    float4 v = reinterpret_cast<const float4*>(W2)[i];
    __half2 a = __floats2half2_rn(v.x, v.y);
    __half2 b = __floats2half2_rn(v.z, v.w);
    reinterpret_cast<__half2*>(g_w2h)[i * 2 + 0] = a;
    reinterpret_cast<__half2*>(g_w2h)[i * 2 + 1] = b;
}

// ---------------------------------------------------------------------------
// Fused FFN kernel
// ---------------------------------------------------------------------------
__global__ __launch_bounds__(NTHREADS, 2)
void ffn_kernel(const float* __restrict__ x, const float* __restrict__ theta,
                const float* __restrict__ W1, float* __restrict__ out)
{
    extern __shared__ char smem[];
    const uint32_t sbase = smem_u32(smem);
    const int tid  = threadIdx.x;
    const int lane = tid & 31;
    const int warp = tid >> 5;      // 0..3
    const int wm   = warp >> 1;     // 0..1  (64 rows)
    const int wn   = warp & 1;      // 0..1  (64 cols)
    const int mbase = blockIdx.y * BM;
    const int nbase = blockIdx.x * BN;

    // Quantum circuit collapsed: mv[w] = cos(theta_w) * cos(x[row, w]).
    const int arow = tid;
    float4 xv = *reinterpret_cast<const float4*>(x + (size_t)(mbase + arow) * EDIM);
    float4 mv;
    mv.x = cosf(theta[0]) * cosf(xv.x);
    mv.y = cosf(theta[1]) * cosf(xv.y);
    mv.z = cosf(theta[2]) * cosf(xv.z);
    mv.w = cosf(theta[3]) * cosf(xv.w);

    float acc[4][8][4];
#pragma unroll
    for (int a = 0; a < 4; a++)
#pragma unroll
        for (int b = 0; b < 8; b++)
#pragma unroll
            for (int c = 0; c < 4; c++) acc[a][b][c] = 0.f;

    // A producer: H[row,k] = relu(mv . W1[k]) in fp16, SW128 layout.
    auto computeA = [&](int kt, int buf) {
        const float4* w1p = reinterpret_cast<const float4*>(W1) + kt * BK;
        char* abase = smem + buf * SM_ABUF;
        const uint32_t swrow = ((uint32_t)arow & 7u) << 4;
        const uint32_t rb = (uint32_t)arow * 128u;
#pragma unroll
        for (int j = 0; j < 64; j += 8) {
            uint32_t v[4];
#pragma unroll
            for (int q = 0; q < 4; q++) {
                float4 wa = w1p[j + 2 * q];
                float4 wb = w1p[j + 2 * q + 1];
                float h0 = fmaf(mv.x, wa.x, fmaf(mv.y, wa.y, fmaf(mv.z, wa.z, mv.w * wa.w)));
                float h1 = fmaf(mv.x, wb.x, fmaf(mv.y, wb.y, fmaf(mv.z, wb.z, mv.w * wb.w)));
                __half2 hh = __floats2half2_rn(fmaxf(h0, 0.f), fmaxf(h1, 0.f));
                v[q] = *reinterpret_cast<uint32_t*>(&hh);
            }
            uint32_t c = (uint32_t)j * 2u;                  // byte col, mult of 16
            *reinterpret_cast<uint4*>(abase + rb + (c ^ swrow)) =
                make_uint4(v[0], v[1], v[2], v[3]);
        }
    };

    // B tile: 128 rows(n) x 64 halfs (128B rows), cp.async 16B chunks, SW128
    auto loadB = [&](int kt, int buf) {
        char* bb = smem + SM_B0 + buf * SM_BBUF;
#pragma unroll
        for (int q = 0; q < 8; q++) {
            int f  = tid + q * NTHREADS;   // 0..1023 16B slots
            int n  = f >> 3, kq = f & 7;
            const __half* src = g_w2h + (size_t)(nbase + n) * FFN + kt * BK + kq * 8;
            uint32_t c  = (uint32_t)kq * 16u;
            uint32_t ds = (uint32_t)__cvta_generic_to_shared(bb) + (uint32_t)n * 128u +
                          (c ^ (((uint32_t)n & 7u) << 4));
            asm volatile("cp.async.cg.shared.global [%0], [%1], 16;" :: "r"(ds), "l"(src));
        }
        asm volatile("cp.async.commit_group;");
    };

    // ldmatrix per-lane address components (r&7 == lane&7 for all tiles)
    const uint32_t swl = ((uint32_t)lane & 7u) << 4;
    const int rlo = ((lane >> 3) & 1) * 8 + (lane & 7);   // row-within-16 for A
    const int akb = ((lane >> 4) & 1) * 16;               // k-byte half for A
    const int nlo = ((lane >> 4) & 1) * 8 + (lane & 7);   // row-within-16 for B
    const int bkb = ((lane >> 3) & 1) * 16;               // k-byte half for B

    // Double-buffered fragment registers
    uint32_t afr[2][4][4];
    uint32_t bfr[2][8][2];

    auto loadFrags = [&](uint32_t Ab, uint32_t Bb, int ks, int fb) {
#pragma unroll
        for (int mt = 0; mt < 4; mt++) {
            int r = wm * 64 + mt * 16 + rlo;
            uint32_t addr = Ab + (uint32_t)r * 128u + (((uint32_t)(ks * 32 + akb)) ^ swl);
            asm volatile("ldmatrix.sync.aligned.m8n8.x4.shared.b16 {%0,%1,%2,%3}, [%4];"
                         : "=r"(afr[fb][mt][0]), "=r"(afr[fb][mt][1]),
                           "=r"(afr[fb][mt][2]), "=r"(afr[fb][mt][3]) : "r"(addr));
        }
#pragma unroll
        for (int nt2 = 0; nt2 < 4; nt2++) {
            int n = wn * 64 + nt2 * 16 + nlo;
            uint32_t addr = Bb + (uint32_t)n * 128u + (((uint32_t)(ks * 32 + bkb)) ^ swl);
            asm volatile("ldmatrix.sync.aligned.m8n8.x4.shared.b16 {%0,%1,%2,%3}, [%4];"
                         : "=r"(bfr[fb][nt2 * 2][0]),     "=r"(bfr[fb][nt2 * 2][1]),
                           "=r"(bfr[fb][nt2 * 2 + 1][0]), "=r"(bfr[fb][nt2 * 2 + 1][1]) : "r"(addr));
        }
    };

    auto mmaStep = [&](int fb) {
#pragma unroll
        for (int mt = 0; mt < 4; mt++)
#pragma unroll
            for (int nt = 0; nt < 8; nt++) {
                float* d = acc[mt][nt];
                asm volatile(
                    "mma.sync.aligned.m16n8k16.row.col.f32.f16.f16.f32 "
                    "{%0,%1,%2,%3}, {%4,%5,%6,%7}, {%8,%9}, {%0,%1,%2,%3};"
                    : "+f"(d[0]), "+f"(d[1]), "+f"(d[2]), "+f"(d[3])
                    : "r"(afr[fb][mt][0]), "r"(afr[fb][mt][1]),
                      "r"(afr[fb][mt][2]), "r"(afr[fb][mt][3]),
                      "r"(bfr[fb][nt][0]), "r"(bfr[fb][nt][1]));
            }
    };

    // Prologue
    computeA(0, 0);
    loadB(0, 0);

    for (int kt = 0; kt < KTILES; kt++) {
        asm volatile("cp.async.wait_group 0;");
        __syncthreads();
        const int buf = kt & 1;
        const uint32_t Ab = sbase + buf * SM_ABUF;
        const uint32_t Bb = sbase + SM_B0 + buf * SM_BBUF;
        // Prefetch frags for ks=0; latency covered by loadB/computeA below.
        loadFrags(Ab, Bb, 0, 0);
        if (kt + 1 < KTILES) {
            loadB(kt + 1, buf ^ 1);
            computeA(kt + 1, buf ^ 1);
        }
#pragma unroll
        for (int ks = 0; ks < 4; ks++) {
            const int fb = ks & 1;
            if (ks < 3) loadFrags(Ab, Bb, ks + 1, fb ^ 1);  // covered by MMAs of ks
            mmaStep(fb);
        }
    }

    // Epilogue: fp32 stores
#pragma unroll
    for (int mt = 0; mt < 4; mt++) {
        int r0 = mbase + wm * 64 + mt * 16 + (lane >> 2);
#pragma unroll
        for (int nt = 0; nt < 8; nt++) {
            int c0 = nbase + wn * 64 + nt * 8 + (lane & 3) * 2;
            *reinterpret_cast<float2*>(out + (size_t)r0 * EDIM + c0) =
                make_float2(acc[mt][nt][0], acc[mt][nt][1]);
            *reinterpret_cast<float2*>(out + (size_t)(r0 + 8) * EDIM + c0) =
                make_float2(acc[mt][nt][2], acc[mt][nt][3]);
        }
    }
}

// ---------------------------------------------------------------------------
extern "C" void kernel_launch(void* const* d_in, const int* in_sizes, int n_in,
                              void* d_out, int out_size) {
    const float* x     = (const float*)d_in[0];
    const float* theta = (const float*)d_in[1];
    const float* W1    = (const float*)d_in[2];
    const float* W2    = (const float*)d_in[3];
    float* out = (float*)d_out;

    cudaFuncSetAttribute(ffn_kernel, cudaFuncAttributeMaxDynamicSharedMemorySize, SMEM_TOTAL);

    w2cvt_kernel<<<(EDIM * FFN / 4) / 256, 256>>>(W2);

    dim3 grid(EDIM / BN, NTOK / BM);   // (4, 256)
    ffn_kernel<<<grid, NTHREADS, SMEM_TOTAL>>>(x, theta, W1, out);
}

// round 10
// speedup vs baseline: 1.7468x; 1.7468x over previous
#include <cuda_runtime.h>
#include <cuda_fp16.h>
#include <cstdint>

// ---------------------------------------------------------------------------
// QFeedForward: out = relu( (cos(theta)*cos(x[...,:4])) @ W1^T ) @ W2^T
// Split design:
//   k1: w2cvt    - W2 -> fp16
//   k2: h_kernel - H = relu( (cos(theta)*cos(x[:, :4])) @ W1^T ) -> fp16
//   k3: gemm     - out = H @ W2h^T, fp16 HMMA m16n8k16, fp32 acc.
// GEMM: CTA 128x128, 4 warps of 64x64, 128 thr, 2 CTA/SM, DOUBLE-buffered
// cp.async pipeline (SMEM 65536 B — >=98KB configs deterministically kill the
// harness container; 65536 has passed 3x).
// ---------------------------------------------------------------------------

#define NTOK 32768
#define EDIM 512
#define FFN  2048

#define BM 128
#define BN 128
#define BK 64
#define KTILES (FFN / BK)            // 32
#define NTHREADS 128

#define SM_ABUF 16384                // 128 rows x 128B (64 halfs), SW128
#define SM_BBUF 16384
#define SM_B0   (2 * SM_ABUF)
#define SMEM_TOTAL (2 * (SM_ABUF + SM_BBUF))   // 65536 B -> 2 CTAs/SM

__device__ __half g_w2h[EDIM * FFN];           // 2 MB
__device__ __half g_h[(size_t)NTOK * FFN];     // 128 MB scratch for H

__device__ __forceinline__ uint32_t smem_u32(const void* p) {
    uint32_t a;
    asm("{ .reg .u64 t; cvta.to.shared.u64 t, %1; cvt.u32.u64 %0, t; }" : "=r"(a) : "l"(p));
    return a;
}

// ---------------------------------------------------------------------------
// W2 -> fp16
// ---------------------------------------------------------------------------
__global__ void w2cvt_kernel(const float* __restrict__ W2) {
    int i = blockIdx.x * blockDim.x + threadIdx.x;   // float4 index
    float4 v = reinterpret_cast<const float4*>(W2)[i];
    __half2 a = __floats2half2_rn(v.x, v.y);
    __half2 b = __floats2half2_rn(v.z, v.w);
    reinterpret_cast<__half2*>(g_w2h)[i * 2 + 0] = a;
    reinterpret_cast<__half2*>(g_w2h)[i * 2 + 1] = b;
}

// ---------------------------------------------------------------------------
// H writer: H[r,k] = relu( sum_w cos(theta_w)*cos(x[r,w]) * W1[k,w] ), fp16.
// Block 256 thr = 8 warps; warp handles 32 rows x 16 k.
// ---------------------------------------------------------------------------
__global__ __launch_bounds__(256)
void h_kernel(const float* __restrict__ x, const float* __restrict__ theta,
              const float* __restrict__ W1) {
    const int lane = threadIdx.x & 31;
    const int warp = threadIdx.x >> 5;
    const int row  = blockIdx.y * 32 + lane;
    const int k0   = blockIdx.x * 128 + warp * 16;

    float4 xv = *reinterpret_cast<const float4*>(x + (size_t)row * EDIM);
    float4 mv;
    mv.x = cosf(theta[0]) * cosf(xv.x);
    mv.y = cosf(theta[1]) * cosf(xv.y);
    mv.z = cosf(theta[2]) * cosf(xv.z);
    mv.w = cosf(theta[3]) * cosf(xv.w);

    const float4* w1p = reinterpret_cast<const float4*>(W1) + k0;
    uint32_t hv[8];
#pragma unroll
    for (int j = 0; j < 16; j += 2) {
        float4 wa = w1p[j], wb = w1p[j + 1];
        float h0 = fmaf(mv.x, wa.x, fmaf(mv.y, wa.y, fmaf(mv.z, wa.z, mv.w * wa.w)));
        float h1 = fmaf(mv.x, wb.x, fmaf(mv.y, wb.y, fmaf(mv.z, wb.z, mv.w * wb.w)));
        __half2 hh = __floats2half2_rn(fmaxf(h0, 0.f), fmaxf(h1, 0.f));
        hv[j >> 1] = *reinterpret_cast<uint32_t*>(&hh);
    }
    __half* dst = g_h + (size_t)row * FFN + k0;
    *reinterpret_cast<uint4*>(dst)     = make_uint4(hv[0], hv[1], hv[2], hv[3]);
    *reinterpret_cast<uint4*>(dst + 8) = make_uint4(hv[4], hv[5], hv[6], hv[7]);
}

// ---------------------------------------------------------------------------
// GEMM: out = H @ W2h^T
// ---------------------------------------------------------------------------
__global__ __launch_bounds__(NTHREADS, 2)
void gemm_kernel(float* __restrict__ out)
{
    extern __shared__ char smem[];
    const uint32_t sbase = smem_u32(smem);
    const int tid  = threadIdx.x;
    const int lane = tid & 31;
    const int warp = tid >> 5;      // 0..3
    const int wm   = warp >> 1;     // 0..1
    const int wn   = warp & 1;      // 0..1
    const int mbase = blockIdx.y * BM;
    const int nbase = blockIdx.x * BN;

    float acc[4][8][4];
#pragma unroll
    for (int a = 0; a < 4; a++)
#pragma unroll
        for (int b = 0; b < 8; b++)
#pragma unroll
            for (int c = 0; c < 4; c++) acc[a][b][c] = 0.f;

    // A tile: rows of H (128 x 64 halfs = 128B rows), SW128 dst
    auto loadA = [&](int kt, int st) {
        char* ab = smem + st * SM_ABUF;
#pragma unroll
        for (int q = 0; q < 8; q++) {
            int f = tid + q * NTHREADS;   // 0..1023
            int r = f >> 3, kq = f & 7;
            const __half* src = g_h + (size_t)(mbase + r) * FFN + kt * BK + kq * 8;
            uint32_t c  = (uint32_t)kq * 16u;
            uint32_t ds = (uint32_t)__cvta_generic_to_shared(ab) + (uint32_t)r * 128u +
                          (c ^ (((uint32_t)r & 7u) << 4));
            asm volatile("cp.async.cg.shared.global [%0], [%1], 16;" :: "r"(ds), "l"(src));
        }
    };
    // B tile: rows of W2h (128 x 64 halfs)
    auto loadB = [&](int kt, int st) {
        char* bb = smem + SM_B0 + st * SM_BBUF;
#pragma unroll
        for (int q = 0; q < 8; q++) {
            int f = tid + q * NTHREADS;
            int n = f >> 3, kq = f & 7;
            const __half* src = g_w2h + (size_t)(nbase + n) * FFN + kt * BK + kq * 8;
            uint32_t c  = (uint32_t)kq * 16u;
            uint32_t ds = (uint32_t)__cvta_generic_to_shared(bb) + (uint32_t)n * 128u +
                          (c ^ (((uint32_t)n & 7u) << 4));
            asm volatile("cp.async.cg.shared.global [%0], [%1], 16;" :: "r"(ds), "l"(src));
        }
    };

    // ldmatrix per-lane address components
    const uint32_t swl = ((uint32_t)lane & 7u) << 4;
    const int rlo = ((lane >> 3) & 1) * 8 + (lane & 7);
    const int akb = ((lane >> 4) & 1) * 16;
    const int nlo = ((lane >> 4) & 1) * 8 + (lane & 7);
    const int bkb = ((lane >> 3) & 1) * 16;

    // Prologue
    loadA(0, 0); loadB(0, 0);
    asm volatile("cp.async.commit_group;");

    for (int kt = 0; kt < KTILES; kt++) {
        asm volatile("cp.async.wait_group 0;");
        __syncthreads();
        const int buf = kt & 1;
        if (kt + 1 < KTILES) {
            loadA(kt + 1, buf ^ 1);
            loadB(kt + 1, buf ^ 1);
            asm volatile("cp.async.commit_group;");
        }
        const uint32_t Ab = sbase + buf * SM_ABUF;
        const uint32_t Bb = sbase + SM_B0 + buf * SM_BBUF;
#pragma unroll
        for (int ks = 0; ks < 4; ks++) {
            uint32_t afr[4][4];
#pragma unroll
            for (int mt = 0; mt < 4; mt++) {
                int r = wm * 64 + mt * 16 + rlo;
                uint32_t addr = Ab + (uint32_t)r * 128u + (((uint32_t)(ks * 32 + akb)) ^ swl);
                asm volatile("ldmatrix.sync.aligned.m8n8.x4.shared.b16 {%0,%1,%2,%3}, [%4];"
                             : "=r"(afr[mt][0]), "=r"(afr[mt][1]),
                               "=r"(afr[mt][2]), "=r"(afr[mt][3]) : "r"(addr));
            }
            uint32_t bfr[8][2];
#pragma unroll
            for (int nt2 = 0; nt2 < 4; nt2++) {
                int n = wn * 64 + nt2 * 16 + nlo;
                uint32_t addr = Bb + (uint32_t)n * 128u + (((uint32_t)(ks * 32 + bkb)) ^ swl);
                asm volatile("ldmatrix.sync.aligned.m8n8.x4.shared.b16 {%0,%1,%2,%3}, [%4];"
                             : "=r"(bfr[nt2 * 2][0]),     "=r"(bfr[nt2 * 2][1]),
                               "=r"(bfr[nt2 * 2 + 1][0]), "=r"(bfr[nt2 * 2 + 1][1]) : "r"(addr));
            }
#pragma unroll
            for (int mt = 0; mt < 4; mt++)
#pragma unroll
                for (int nt = 0; nt < 8; nt++) {
                    float* d = acc[mt][nt];
                    asm volatile(
                        "mma.sync.aligned.m16n8k16.row.col.f32.f16.f16.f32 "
                        "{%0,%1,%2,%3}, {%4,%5,%6,%7}, {%8,%9}, {%0,%1,%2,%3};"
                        : "+f"(d[0]), "+f"(d[1]), "+f"(d[2]), "+f"(d[3])
                        : "r"(afr[mt][0]), "r"(afr[mt][1]), "r"(afr[mt][2]), "r"(afr[mt][3]),
                          "r"(bfr[nt][0]), "r"(bfr[nt][1]));
                }
        }
    }

    // Epilogue: fp32 stores
#pragma unroll
    for (int mt = 0; mt < 4; mt++) {
        int r0 = mbase + wm * 64 + mt * 16 + (lane >> 2);
#pragma unroll
        for (int nt = 0; nt < 8; nt++) {
            int c0 = nbase + wn * 64 + nt * 8 + (lane & 3) * 2;
            *reinterpret_cast<float2*>(out + (size_t)r0 * EDIM + c0) =
                make_float2(acc[mt][nt][0], acc[mt][nt][1]);
            *reinterpret_cast<float2*>(out + (size_t)(r0 + 8) * EDIM + c0) =
                make_float2(acc[mt][nt][2], acc[mt][nt][3]);
        }
    }
}

// ---------------------------------------------------------------------------
extern "C" void kernel_launch(void* const* d_in, const int* in_sizes, int n_in,
                              void* d_out, int out_size) {
    const float* x     = (const float*)d_in[0];
    const float* theta = (const float*)d_in[1];
    const float* W1    = (const float*)d_in[2];
    const float* W2    = (const float*)d_in[3];
    float* out = (float*)d_out;

    cudaFuncSetAttribute(gemm_kernel, cudaFuncAttributeMaxDynamicSharedMemorySize, SMEM_TOTAL);

    w2cvt_kernel<<<(EDIM * FFN / 4) / 256, 256>>>(W2);

    dim3 hgrid(FFN / 128, NTOK / 32);          // (16, 1024)
    h_kernel<<<hgrid, 256>>>(x, theta, W1);

    dim3 ggrid(EDIM / BN, NTOK / BM);          // (4, 256)
    gemm_kernel<<<ggrid, NTHREADS, SMEM_TOTAL>>>(out);
}